// round 1
// baseline (speedup 1.0000x reference)
#include <cuda_runtime.h>
#include <math.h>

#define NN   100000
#define NE   1600000
#define INF  16
#define HIDD 128
#define NL   8
#define NB_SCAN 391   /* ceil(NN/256) */

// ---------------- device scratch (no allocs allowed) ----------------
__device__ __align__(16) float g_h[NN * HIDD];
__device__ __align__(16) float g_z[NN * HIDD];     // also reused as y2
__device__ __align__(16) float g_y1[NN * HIDD];
__device__ __align__(16) float g_skip[NN * HIDD];
__device__ __align__(16) float g_z0[NN * INF];
__device__ int   g_deg[NN];
__device__ int   g_row[NN];
__device__ int   g_fill[NN];
__device__ int   g_csr[NE];
__device__ int   g_bsum[512];
__device__ __align__(16) float g_stats[256];
__device__ __align__(16) float g_scale[HIDD];
__device__ __align__(16) float g_shift[HIDD];

// ---------------- helpers ----------------
__device__ __forceinline__ float4 f4ld(const float* p) { return *(const float4*)p; }

// ---------------- CSR build ----------------
__global__ void k_zero() {
    int i = blockIdx.x * blockDim.x + threadIdx.x;
    if (i < NN) g_deg[i] = 0;
    if (i < 256) g_stats[i] = 0.f;
}

__global__ void k_hist(const int* __restrict__ dst) {
    int e = blockIdx.x * blockDim.x + threadIdx.x;
    if (e < NE) atomicAdd(&g_deg[dst[e]], 1);
}

__global__ void k_scan1() {
    __shared__ int sh[256];
    int t = threadIdx.x;
    int i = blockIdx.x * 256 + t;
    int v = (i < NN) ? g_deg[i] : 0;
    sh[t] = v;
    __syncthreads();
    #pragma unroll
    for (int off = 1; off < 256; off <<= 1) {
        int add = (t >= off) ? sh[t - off] : 0;
        __syncthreads();
        sh[t] += add;
        __syncthreads();
    }
    if (i < NN) g_row[i] = sh[t] - v;        // exclusive within block
    if (t == 255) g_bsum[blockIdx.x] = sh[255];
}

__global__ void k_scan2() {
    __shared__ int sh[512];
    int t = threadIdx.x;
    int v = (t < NB_SCAN) ? g_bsum[t] : 0;
    sh[t] = v;
    __syncthreads();
    #pragma unroll
    for (int off = 1; off < 512; off <<= 1) {
        int add = (t >= off) ? sh[t - off] : 0;
        __syncthreads();
        sh[t] += add;
        __syncthreads();
    }
    g_bsum[t] = sh[t] - v;                   // exclusive block offsets
}

__global__ void k_scan3() {
    int i = blockIdx.x * blockDim.x + threadIdx.x;
    if (i < NN) {
        int rs = g_row[i] + g_bsum[i >> 8];
        g_row[i] = rs;
        g_fill[i] = rs;
    }
}

__global__ void k_fill(const int* __restrict__ src, const int* __restrict__ dst) {
    int e = blockIdx.x * blockDim.x + threadIdx.x;
    if (e < NE) {
        int d = dst[e];
        int p = atomicAdd(&g_fill[d], 1);
        g_csr[p] = src[e];
    }
}

// ---------------- aggregation: z = (1+eps)*h + sum_{src in N(dst)} h[src] ----------------
// Hidden layers: 1 warp per node, each lane owns a float4 (128 cols).
__global__ void k_agg(const float* __restrict__ hin, float* __restrict__ zout,
                      const float* __restrict__ eps, int layer) {
    int gt = blockIdx.x * blockDim.x + threadIdx.x;
    int node = gt >> 5;
    int lane = gt & 31;
    if (node >= NN) return;
    float e1 = 1.f + __ldg(&eps[layer]);
    const float4* h4 = (const float4*)hin;
    int start = g_row[node];
    int d = g_deg[node];
    float4 a = h4[(size_t)node * 32 + lane];
    float4 acc0 = make_float4(a.x * e1, a.y * e1, a.z * e1, a.w * e1);
    float4 acc1 = make_float4(0.f, 0.f, 0.f, 0.f);
    int j = 0;
    for (; j + 2 <= d; j += 2) {
        int s0 = __ldg(&g_csr[start + j]);
        int s1 = __ldg(&g_csr[start + j + 1]);
        float4 v0 = h4[(size_t)s0 * 32 + lane];
        float4 v1 = h4[(size_t)s1 * 32 + lane];
        acc0.x += v0.x; acc0.y += v0.y; acc0.z += v0.z; acc0.w += v0.w;
        acc1.x += v1.x; acc1.y += v1.y; acc1.z += v1.z; acc1.w += v1.w;
    }
    if (j < d) {
        int s = __ldg(&g_csr[start + j]);
        float4 v = h4[(size_t)s * 32 + lane];
        acc0.x += v.x; acc0.y += v.y; acc0.z += v.z; acc0.w += v.w;
    }
    float4 o = make_float4(acc0.x + acc1.x, acc0.y + acc1.y, acc0.z + acc1.z, acc0.w + acc1.w);
    ((float4*)zout)[(size_t)node * 32 + lane] = o;
}

// Layer 0: 16 cols, 4 threads per node, one float4 each.
__global__ void k_agg0(const float* __restrict__ x, float* __restrict__ z0,
                       const float* __restrict__ eps) {
    int t = blockIdx.x * blockDim.x + threadIdx.x;
    if (t >= NN * 4) return;
    int n = t >> 2;
    float e1 = 1.f + __ldg(&eps[0]);
    const float4* x4 = (const float4*)x;
    float4 a = x4[t];
    float4 acc = make_float4(a.x * e1, a.y * e1, a.z * e1, a.w * e1);
    int start = g_row[n];
    int d = g_deg[n];
    int q = t & 3;
    for (int j = 0; j < d; j++) {
        int s = __ldg(&g_csr[start + j]);
        float4 v = x4[(size_t)s * 4 + q];
        acc.x += v.x; acc.y += v.y; acc.z += v.z; acc.w += v.w;
    }
    ((float4*)z0)[t] = acc;
}

// ---------------- GEMM: C[NN,128] = f(A)[NN,K] @ W[K,128] + bias, + column stats ----------------
// MODE 0: identity A, MODE 1: relu(A*scale[k]+shift[k]), MODE 2: 0.25*A
#define ASTR 136
template<int MODE>
__global__ void __launch_bounds__(256)
k_gemm(const float* __restrict__ A, int K, const float* __restrict__ W,
       const float* __restrict__ bias, float* __restrict__ C) {
    extern __shared__ float smem[];
    float* Ws = smem;                 // K*128
    float* As = smem + K * 128;       // 8*ASTR
    const int tid = threadIdx.x;
    const int tx = tid & 15;
    const int ty = tid >> 4;
    const int m0 = blockIdx.x * 128;

    for (int idx = tid * 4; idx < K * 128; idx += 1024)
        *(float4*)(Ws + idx) = f4ld(W + idx);

    float acc[8][8];
    #pragma unroll
    for (int i = 0; i < 8; i++)
        #pragma unroll
        for (int j = 0; j < 8; j++) acc[i][j] = 0.f;

    const int r = tid >> 1;
    const int kq = (tid & 1) * 4;
    const int m = m0 + r;

    for (int k0 = 0; k0 < K; k0 += 8) {
        float4 a = make_float4(0.f, 0.f, 0.f, 0.f);
        if (m < NN) a = f4ld(A + (size_t)m * K + k0 + kq);
        if (MODE == 1) {
            float4 sc = f4ld(g_scale + k0 + kq);
            float4 sh = f4ld(g_shift + k0 + kq);
            a.x = fmaxf(fmaf(a.x, sc.x, sh.x), 0.f);
            a.y = fmaxf(fmaf(a.y, sc.y, sh.y), 0.f);
            a.z = fmaxf(fmaf(a.z, sc.z, sh.z), 0.f);
            a.w = fmaxf(fmaf(a.w, sc.w, sh.w), 0.f);
        } else if (MODE == 2) {
            a.x *= 0.25f; a.y *= 0.25f; a.z *= 0.25f; a.w *= 0.25f;
        }
        __syncthreads();   // prev compute done (iter0: W load done)
        As[(kq + 0) * ASTR + r] = a.x;
        As[(kq + 1) * ASTR + r] = a.y;
        As[(kq + 2) * ASTR + r] = a.z;
        As[(kq + 3) * ASTR + r] = a.w;
        __syncthreads();
        #pragma unroll
        for (int kk = 0; kk < 8; kk++) {
            float4 a0 = *(float4*)(As + kk * ASTR + ty * 8);
            float4 a1 = *(float4*)(As + kk * ASTR + ty * 8 + 4);
            float4 b0 = *(float4*)(Ws + (k0 + kk) * 128 + tx * 4);
            float4 b1 = *(float4*)(Ws + (k0 + kk) * 128 + 64 + tx * 4);
            float av[8] = {a0.x, a0.y, a0.z, a0.w, a1.x, a1.y, a1.z, a1.w};
            float bv[8] = {b0.x, b0.y, b0.z, b0.w, b1.x, b1.y, b1.z, b1.w};
            #pragma unroll
            for (int i = 0; i < 8; i++)
                #pragma unroll
                for (int j = 0; j < 8; j++)
                    acc[i][j] = fmaf(av[i], bv[j], acc[i][j]);
        }
    }

    // epilogue: bias, store, column stats
    float bj[8];
    #pragma unroll
    for (int j = 0; j < 4; j++) bj[j] = __ldg(&bias[tx * 4 + j]);
    #pragma unroll
    for (int j = 4; j < 8; j++) bj[j] = __ldg(&bias[64 + tx * 4 + (j - 4)]);

    float s[8], q[8];
    #pragma unroll
    for (int j = 0; j < 8; j++) { s[j] = 0.f; q[j] = 0.f; }

    #pragma unroll
    for (int i = 0; i < 8; i++) {
        int mm = m0 + ty * 8 + i;
        if (mm < NN) {
            float c[8];
            #pragma unroll
            for (int j = 0; j < 8; j++) {
                c[j] = acc[i][j] + bj[j];
                s[j] += c[j];
                q[j] += c[j] * c[j];
            }
            *(float4*)(C + (size_t)mm * 128 + tx * 4)      = make_float4(c[0], c[1], c[2], c[3]);
            *(float4*)(C + (size_t)mm * 128 + 64 + tx * 4) = make_float4(c[4], c[5], c[6], c[7]);
        }
    }

    __syncthreads();
    float* red = smem;   // reuse Ws region (>=256 floats)
    red[tid] = 0.f;
    __syncthreads();
    #pragma unroll
    for (int j = 0; j < 4; j++) {
        atomicAdd(&red[tx * 4 + j], s[j]);
        atomicAdd(&red[128 + tx * 4 + j], q[j]);
        atomicAdd(&red[64 + tx * 4 + j], s[j + 4]);
        atomicAdd(&red[128 + 64 + tx * 4 + j], q[j + 4]);
    }
    __syncthreads();
    atomicAdd(&g_stats[tid], red[tid]);
}

// ---------------- BN finalize: scale/shift from stats; re-zero stats ----------------
__global__ void k_finalize(const float* __restrict__ gamma, const float* __restrict__ beta) {
    int t = threadIdx.x;
    float su = g_stats[t];
    float sq = g_stats[128 + t];
    float mean = su * (1.f / NN);
    float var = sq * (1.f / NN) - mean * mean;
    float rstd = rsqrtf(fmaxf(var, 0.f) + 1e-5f);
    float sc = __ldg(&gamma[t]) * rstd;
    g_scale[t] = sc;
    g_shift[t] = __ldg(&beta[t]) - mean * sc;
    g_stats[t] = 0.f;
    g_stats[128 + t] = 0.f;
}

// ---------------- post: h = relu(bn(y2)); optional skip accumulate ----------------
__global__ void k_post(const float* __restrict__ y, float* __restrict__ h, int skipmode) {
    int i = blockIdx.x * blockDim.x + threadIdx.x;   // float4 index
    if (i >= NN * 32) return;
    int c4 = (i & 31) * 4;
    float4 sc = f4ld(g_scale + c4);
    float4 sh = f4ld(g_shift + c4);
    float4 v = ((const float4*)y)[i];
    v.x = fmaxf(fmaf(v.x, sc.x, sh.x), 0.f);
    v.y = fmaxf(fmaf(v.y, sc.y, sh.y), 0.f);
    v.z = fmaxf(fmaf(v.z, sc.z, sh.z), 0.f);
    v.w = fmaxf(fmaf(v.w, sc.w, sh.w), 0.f);
    ((float4*)h)[i] = v;
    if (skipmode == 1) {
        ((float4*)g_skip)[i] = v;
    } else if (skipmode == 2) {
        float4 s = ((float4*)g_skip)[i];
        s.x += v.x; s.y += v.y; s.z += v.z; s.w += v.w;
        ((float4*)g_skip)[i] = s;
    }
}

// ---------------- final: out = sigmoid(relu(bn(yr1)) . Wr2 + br2) ----------------
__global__ void k_final(const float* __restrict__ y, const float* __restrict__ Wr2,
                        const float* __restrict__ br2, float* __restrict__ out) {
    __shared__ float w[128];
    if (threadIdx.x < 128) w[threadIdx.x] = Wr2[threadIdx.x];
    __syncthreads();
    int gt = blockIdx.x * blockDim.x + threadIdx.x;
    int n = gt >> 5;
    int lane = gt & 31;
    if (n >= NN) return;
    float4 v = ((const float4*)y)[(size_t)n * 32 + lane];
    float4 sc = f4ld(g_scale + lane * 4);
    float4 sh = f4ld(g_shift + lane * 4);
    float d = fmaxf(fmaf(v.x, sc.x, sh.x), 0.f) * w[lane * 4 + 0]
            + fmaxf(fmaf(v.y, sc.y, sh.y), 0.f) * w[lane * 4 + 1]
            + fmaxf(fmaf(v.z, sc.z, sh.z), 0.f) * w[lane * 4 + 2]
            + fmaxf(fmaf(v.w, sc.w, sh.w), 0.f) * w[lane * 4 + 3];
    #pragma unroll
    for (int off = 16; off > 0; off >>= 1)
        d += __shfl_xor_sync(0xffffffffu, d, off);
    if (lane == 0) out[n] = 1.f / (1.f + expf(-(d + __ldg(br2))));
}

// ---------------- host ----------------
extern "C" void kernel_launch(void* const* d_in, const int* in_sizes, int n_in,
                              void* d_out, int out_size) {
    const float* x     = (const float*)d_in[0];
    const int*   ei    = (const int*)d_in[1];
    const float* eps   = (const float*)d_in[2];
    const float* W1_0  = (const float*)d_in[3];
    const float* b1_0  = (const float*)d_in[4];
    const float* W1    = (const float*)d_in[5];
    const float* b1    = (const float*)d_in[6];
    const float* g_in  = (const float*)d_in[7];
    const float* be_in = (const float*)d_in[8];
    const float* W2    = (const float*)d_in[9];
    const float* b2    = (const float*)d_in[10];
    const float* g_out = (const float*)d_in[11];
    const float* be_out= (const float*)d_in[12];
    const float* Wr1   = (const float*)d_in[13];
    const float* br1   = (const float*)d_in[14];
    const float* gr    = (const float*)d_in[15];
    const float* ber   = (const float*)d_in[16];
    const float* Wr2   = (const float*)d_in[17];
    const float* br2   = (const float*)d_in[18];
    const int* srcp = ei;
    const int* dstp = ei + NE;

    float *h, *z, *y1, *skip, *z0;
    cudaGetSymbolAddress((void**)&h, g_h);
    cudaGetSymbolAddress((void**)&z, g_z);
    cudaGetSymbolAddress((void**)&y1, g_y1);
    cudaGetSymbolAddress((void**)&skip, g_skip);
    cudaGetSymbolAddress((void**)&z0, g_z0);

    const int SMEM_G128 = (128 * 128 + 8 * ASTR) * (int)sizeof(float);
    const int SMEM_G16  = (16 * 128 + 8 * ASTR) * (int)sizeof(float);
    cudaFuncSetAttribute(k_gemm<0>, cudaFuncAttributeMaxDynamicSharedMemorySize, SMEM_G128);
    cudaFuncSetAttribute(k_gemm<1>, cudaFuncAttributeMaxDynamicSharedMemorySize, SMEM_G128);
    cudaFuncSetAttribute(k_gemm<2>, cudaFuncAttributeMaxDynamicSharedMemorySize, SMEM_G128);

    const int GEMM_BLOCKS = (NN + 127) / 128;   // 782

    // CSR build + stats zero
    k_zero<<<(NN + 255) / 256, 256>>>();
    k_hist<<<(NE + 255) / 256, 256>>>(dstp);
    k_scan1<<<NB_SCAN, 256>>>();
    k_scan2<<<1, 512>>>();
    k_scan3<<<NB_SCAN, 256>>>();
    k_fill<<<(NE + 255) / 256, 256>>>(srcp, dstp);

    for (int i = 0; i < NL; i++) {
        if (i == 0)
            k_agg0<<<(NN * 4 + 255) / 256, 256>>>(x, z0, eps);
        else
            k_agg<<<(NN * 32 + 255) / 256, 256>>>(h, z, eps, i);

        const float* Wa = (i == 0) ? W1_0 : (W1 + (size_t)(i - 1) * HIDD * HIDD);
        const float* ba = (i == 0) ? b1_0 : (b1 + (size_t)(i - 1) * HIDD);
        int K = (i == 0) ? INF : HIDD;
        const float* Ain = (i == 0) ? z0 : z;
        k_gemm<0><<<GEMM_BLOCKS, 256, (i == 0) ? SMEM_G16 : SMEM_G128>>>(Ain, K, Wa, ba, y1);
        k_finalize<<<1, 128>>>(g_in + (size_t)i * HIDD, be_in + (size_t)i * HIDD);

        k_gemm<1><<<GEMM_BLOCKS, 256, SMEM_G128>>>(y1, HIDD, W2 + (size_t)i * HIDD * HIDD,
                                                   b2 + (size_t)i * HIDD, z);
        k_finalize<<<1, 128>>>(g_out + (size_t)i * HIDD, be_out + (size_t)i * HIDD);

        int sm = (i % 2 == 1) ? ((i == 1) ? 1 : 2) : 0;
        k_post<<<(NN * 32 + 255) / 256, 256>>>(z, h, sm);
    }

    // regressor
    k_gemm<2><<<GEMM_BLOCKS, 256, SMEM_G128>>>(skip, HIDD, Wr1, br1, y1);
    k_finalize<<<1, 128>>>(gr, ber);
    k_final<<<(NN * 32 + 255) / 256, 256>>>(y1, Wr2, br2, (float*)d_out);
}

// round 3
// speedup vs baseline: 1.4853x; 1.4853x over previous
#include <cuda_runtime.h>
#include <cuda_bf16.h>
#include <math.h>
#include <stdint.h>

#define NN   100000
#define NE   1600000
#define INF  16
#define HIDD 128
#define NL   8
#define NB_SCAN 391   /* ceil(NN/256) */
#define NTILES 782    /* ceil(NN/128) */

// ---------------- device scratch (no allocs allowed) ----------------
__device__ __align__(16) float g_h[NN * HIDD];
__device__ __align__(16) float g_z[NN * HIDD];
__device__ __align__(16) float g_y1[NN * HIDD];
__device__ __align__(16) float g_skip[NN * HIDD];
__device__ __align__(16) float g_z0[NN * INF];
__device__ int   g_deg[NN];
__device__ int   g_row[NN];
__device__ int   g_fill[NN];
__device__ int   g_csr[NE];
__device__ int   g_bsum[512];
__device__ __align__(16) float g_stats[256];
__device__ __align__(16) float g_scale[HIDD];
__device__ __align__(16) float g_shift[HIDD];
// prepped weights: bf16 hi/lo, n-major [n=128][k pad 136] per image, 17 images
#define BIMG 17408   /* halves per image */
__device__ __align__(16) __nv_bfloat16 g_Bh[17 * BIMG];
__device__ __align__(16) __nv_bfloat16 g_Bl[17 * BIMG];

__device__ __forceinline__ float4 f4ld(const float* p) { return *(const float4*)p; }

__device__ __forceinline__ uint32_t smem_u32(const void* p) {
    uint32_t a;
    asm("{ .reg .u64 t; cvta.to.shared.u64 t, %1; cvt.u32.u64 %0, t; }" : "=r"(a) : "l"(p));
    return a;
}
__device__ __forceinline__ uint32_t pk(__nv_bfloat16 a, __nv_bfloat16 b) {
    __nv_bfloat162 t(a, b);
    return *(uint32_t*)&t;
}

#define LDM4(r, addr) \
    asm volatile("ldmatrix.sync.aligned.m8n8.x4.shared.b16 {%0,%1,%2,%3}, [%4];" \
        : "=r"((r)[0]), "=r"((r)[1]), "=r"((r)[2]), "=r"((r)[3]) : "r"(addr))

#define MMA16(acc, a, b0, b1) \
    asm volatile("mma.sync.aligned.m16n8k16.row.col.f32.bf16.bf16.f32 " \
        "{%0,%1,%2,%3}, {%4,%5,%6,%7}, {%8,%9}, {%0,%1,%2,%3};" \
        : "+f"((acc)[0]), "+f"((acc)[1]), "+f"((acc)[2]), "+f"((acc)[3]) \
        : "r"((a)[0]), "r"((a)[1]), "r"((a)[2]), "r"((a)[3]), "r"(b0), "r"(b1))

// ---------------- CSR build ----------------
__global__ void k_zero() {
    int i = blockIdx.x * blockDim.x + threadIdx.x;
    if (i < NN) g_deg[i] = 0;
    if (i < 256) g_stats[i] = 0.f;
}
__global__ void k_hist(const int* __restrict__ dst) {
    int e = blockIdx.x * blockDim.x + threadIdx.x;
    if (e < NE) atomicAdd(&g_deg[dst[e]], 1);
}
__global__ void k_scan1() {
    __shared__ int sh[256];
    int t = threadIdx.x;
    int i = blockIdx.x * 256 + t;
    int v = (i < NN) ? g_deg[i] : 0;
    sh[t] = v;
    __syncthreads();
    #pragma unroll
    for (int off = 1; off < 256; off <<= 1) {
        int add = (t >= off) ? sh[t - off] : 0;
        __syncthreads();
        sh[t] += add;
        __syncthreads();
    }
    if (i < NN) g_row[i] = sh[t] - v;
    if (t == 255) g_bsum[blockIdx.x] = sh[255];
}
__global__ void k_scan2() {
    __shared__ int sh[512];
    int t = threadIdx.x;
    int v = (t < NB_SCAN) ? g_bsum[t] : 0;
    sh[t] = v;
    __syncthreads();
    #pragma unroll
    for (int off = 1; off < 512; off <<= 1) {
        int add = (t >= off) ? sh[t - off] : 0;
        __syncthreads();
        sh[t] += add;
        __syncthreads();
    }
    g_bsum[t] = sh[t] - v;
}
__global__ void k_scan3() {
    int i = blockIdx.x * blockDim.x + threadIdx.x;
    if (i < NN) {
        int rs = g_row[i] + g_bsum[i >> 8];
        g_row[i] = rs;
        g_fill[i] = rs;
    }
}
__global__ void k_fill(const int* __restrict__ src, const int* __restrict__ dst) {
    int e = blockIdx.x * blockDim.x + threadIdx.x;
    if (e < NE) {
        int d = dst[e];
        int p = atomicAdd(&g_fill[d], 1);
        g_csr[p] = src[e];
    }
}

// ---------------- weight prep: bf16 hi/lo split, n-major [n][k] pad 136 ----------------
// img 0: W1_0 (K=16); 1..7: W1; 8..15: W2; 16: Wr1
__global__ void k_prepw(const float* __restrict__ W1_0, const float* __restrict__ W1,
                        const float* __restrict__ W2, const float* __restrict__ Wr1) {
    int img = blockIdx.y;
    int idx = blockIdx.x * 256 + threadIdx.x;   // over 128*136
    if (idx >= BIMG) return;
    int n = idx / 136;
    int k = idx % 136;
    int Kreal = (img == 0) ? 16 : 128;
    const float* W = (img == 0) ? W1_0
                   : (img <= 7) ? (W1 + (size_t)(img - 1) * 16384)
                   : (img <= 15) ? (W2 + (size_t)(img - 8) * 16384)
                   : Wr1;
    float w = (k < Kreal) ? W[(size_t)k * 128 + n] : 0.f;
    __nv_bfloat16 hi = __float2bfloat16_rn(w);
    __nv_bfloat16 lo = __float2bfloat16_rn(w - __bfloat162float(hi));
    g_Bh[(size_t)img * BIMG + idx] = hi;
    g_Bl[(size_t)img * BIMG + idx] = lo;
}

// ---------------- aggregation ----------------
__global__ void k_agg(const float* __restrict__ hin, float* __restrict__ zout,
                      const float* __restrict__ eps, int layer) {
    int gt = blockIdx.x * blockDim.x + threadIdx.x;
    int node = gt >> 5;
    int lane = gt & 31;
    if (node >= NN) return;
    float e1 = 1.f + __ldg(&eps[layer]);
    const float4* h4 = (const float4*)hin;
    int start = g_row[node];
    int d = g_deg[node];
    float4 a = h4[(size_t)node * 32 + lane];
    float4 acc0 = make_float4(a.x * e1, a.y * e1, a.z * e1, a.w * e1);
    float4 acc1 = make_float4(0.f, 0.f, 0.f, 0.f);
    int j = 0;
    for (; j + 2 <= d; j += 2) {
        int s0 = __ldg(&g_csr[start + j]);
        int s1 = __ldg(&g_csr[start + j + 1]);
        float4 v0 = h4[(size_t)s0 * 32 + lane];
        float4 v1 = h4[(size_t)s1 * 32 + lane];
        acc0.x += v0.x; acc0.y += v0.y; acc0.z += v0.z; acc0.w += v0.w;
        acc1.x += v1.x; acc1.y += v1.y; acc1.z += v1.z; acc1.w += v1.w;
    }
    if (j < d) {
        int s = __ldg(&g_csr[start + j]);
        float4 v = h4[(size_t)s * 32 + lane];
        acc0.x += v.x; acc0.y += v.y; acc0.z += v.z; acc0.w += v.w;
    }
    float4 o = make_float4(acc0.x + acc1.x, acc0.y + acc1.y, acc0.z + acc1.z, acc0.w + acc1.w);
    ((float4*)zout)[(size_t)node * 32 + lane] = o;
}

__global__ void k_agg0(const float* __restrict__ x, float* __restrict__ z0,
                       const float* __restrict__ eps) {
    int t = blockIdx.x * blockDim.x + threadIdx.x;
    if (t >= NN * 4) return;
    int n = t >> 2;
    float e1 = 1.f + __ldg(&eps[0]);
    const float4* x4 = (const float4*)x;
    float4 a = x4[t];
    float4 acc = make_float4(a.x * e1, a.y * e1, a.z * e1, a.w * e1);
    int start = g_row[n];
    int d = g_deg[n];
    int q = t & 3;
    for (int j = 0; j < d; j++) {
        int s = __ldg(&g_csr[start + j]);
        float4 v = x4[(size_t)s * 4 + q];
        acc.x += v.x; acc.y += v.y; acc.z += v.z; acc.w += v.w;
    }
    ((float4*)z0)[t] = acc;
}

// ---------------- mma.sync bf16x3 GEMM, persistent ----------------
// C[NN,128] = f(A)[NN,KR] @ W[KR,128] + bias; column sum/sumsq into g_stats.
// MODE 0: identity; 1: relu(A*scale+shift); 2: A*0.25
// smem (bytes): Ah 34816 | Al 34816 | Bh 34816 | Bl 34816 | bias 512 | red 1024
#define SM_AH 0
#define SM_AL 34816
#define SM_BH 69632
#define SM_BL 104448
#define SM_BI 139264
#define SM_RD 139776
#define SMEM_MG 140800

template<int MODE, int KR>
__global__ void __launch_bounds__(256, 1)
k_mgemm(const float* __restrict__ A, const __nv_bfloat16* __restrict__ Bh,
        const __nv_bfloat16* __restrict__ Bl, const float* __restrict__ bias,
        float* __restrict__ C) {
    extern __shared__ char smem[];
    uint32_t sb = smem_u32(smem);
    float* fs = (float*)smem;
    const int tid = threadIdx.x, lane = tid & 31, wid = tid >> 5;
    const int wm = wid >> 2, wn = wid & 3;

    // resident B
    for (int i = tid * 16; i < 34816; i += 4096) {
        *(uint4*)(smem + SM_BH + i) = *(const uint4*)((const char*)Bh + i);
        *(uint4*)(smem + SM_BL + i) = *(const uint4*)((const char*)Bl + i);
    }
    if (tid < 128) {
        fs[(SM_BI >> 2) + tid] = __ldg(&bias[tid]);
        fs[(SM_RD >> 2) + tid] = 0.f;
        fs[(SM_RD >> 2) + 128 + tid] = 0.f;
    }

    // ldmatrix lane addressing
    const uint32_t a_row = (lane & 7) + ((lane >> 3) & 1) * 8;
    const uint32_t a_kb  = (lane >> 4) * 16;
    const uint32_t b_n   = (lane & 7) + ((lane >> 4) & 1) * 8;
    const uint32_t b_kb  = ((lane >> 3) & 1) * 16;

    constexpr int F4R = KR / 4;           // float4 per row
    constexpr int NIT = (128 * F4R) / 256; // A-load iters per thread

    for (int tile = blockIdx.x; tile < NTILES; tile += gridDim.x) {
        int mb = tile * 128;
        __syncthreads();   // prior tile's smem reads done

        // ---- load A tile, transform, split to bf16 hi/lo ----
        #pragma unroll
        for (int i = 0; i < NIT; i++) {
            int idx = tid + i * 256;
            int row = idx / F4R;
            int c = (idx % F4R) * 4;
            float4 v = make_float4(0.f, 0.f, 0.f, 0.f);
            if (mb + row < NN) v = f4ld(A + (size_t)(mb + row) * KR + c);
            if (MODE == 1) {
                float4 sc = f4ld(g_scale + c);
                float4 sh = f4ld(g_shift + c);
                v.x = fmaxf(fmaf(v.x, sc.x, sh.x), 0.f);
                v.y = fmaxf(fmaf(v.y, sc.y, sh.y), 0.f);
                v.z = fmaxf(fmaf(v.z, sc.z, sh.z), 0.f);
                v.w = fmaxf(fmaf(v.w, sc.w, sh.w), 0.f);
            } else if (MODE == 2) {
                v.x *= 0.25f; v.y *= 0.25f; v.z *= 0.25f; v.w *= 0.25f;
            }
            __nv_bfloat16 hx = __float2bfloat16_rn(v.x);
            __nv_bfloat16 hy = __float2bfloat16_rn(v.y);
            __nv_bfloat16 hz = __float2bfloat16_rn(v.z);
            __nv_bfloat16 hw = __float2bfloat16_rn(v.w);
            __nv_bfloat16 lx = __float2bfloat16_rn(v.x - __bfloat162float(hx));
            __nv_bfloat16 ly = __float2bfloat16_rn(v.y - __bfloat162float(hy));
            __nv_bfloat16 lz = __float2bfloat16_rn(v.z - __bfloat162float(hz));
            __nv_bfloat16 lw = __float2bfloat16_rn(v.w - __bfloat162float(hw));
            uint32_t off = (uint32_t)row * 272u + (uint32_t)c * 2u;
            *(uint2*)(smem + SM_AH + off) = make_uint2(pk(hx, hy), pk(hz, hw));
            *(uint2*)(smem + SM_AL + off) = make_uint2(pk(lx, ly), pk(lz, lw));
        }
        __syncthreads();

        // ---- mma ----
        float acc[4][4][4];
        #pragma unroll
        for (int mi = 0; mi < 4; mi++)
            #pragma unroll
            for (int ni = 0; ni < 4; ni++)
                #pragma unroll
                for (int r = 0; r < 4; r++) acc[mi][ni][r] = 0.f;

        #pragma unroll
        for (int ks = 0; ks < KR / 16; ks++) {
            uint32_t kb = ks * 32;
            uint32_t ah[4][4], al[4][4], bh2[2][4], bl2[2][4];
            #pragma unroll
            for (int mi = 0; mi < 4; mi++) {
                uint32_t addr = sb + SM_AH + (wm * 64 + mi * 16 + a_row) * 272 + a_kb + kb;
                LDM4(ah[mi], addr);
                LDM4(al[mi], addr + 34816);
            }
            #pragma unroll
            for (int g = 0; g < 2; g++) {
                uint32_t addr = sb + SM_BH + (wn * 32 + g * 16 + b_n) * 272 + b_kb + kb;
                LDM4(bh2[g], addr);
                LDM4(bl2[g], addr + 34816);
            }
            #pragma unroll
            for (int mi = 0; mi < 4; mi++)
                #pragma unroll
                for (int ni = 0; ni < 4; ni++) {
                    uint32_t b0h = bh2[ni >> 1][(ni & 1) * 2];
                    uint32_t b1h = bh2[ni >> 1][(ni & 1) * 2 + 1];
                    uint32_t b0l = bl2[ni >> 1][(ni & 1) * 2];
                    uint32_t b1l = bl2[ni >> 1][(ni & 1) * 2 + 1];
                    MMA16(acc[mi][ni], ah[mi], b0h, b1h);
                    MMA16(acc[mi][ni], al[mi], b0h, b1h);
                    MMA16(acc[mi][ni], ah[mi], b0l, b1l);
                }
        }

        // ---- epilogue: bias + store + column stats ----
        float s0[4], s1[4], q0[4], q1[4];
        #pragma unroll
        for (int ni = 0; ni < 4; ni++) { s0[ni] = s1[ni] = q0[ni] = q1[ni] = 0.f; }
        #pragma unroll
        for (int mi = 0; mi < 4; mi++) {
            int row0 = mb + wm * 64 + mi * 16 + (lane >> 2);
            int row1 = row0 + 8;
            #pragma unroll
            for (int ni = 0; ni < 4; ni++) {
                int col = wn * 32 + ni * 8 + (lane & 3) * 2;
                float bb0 = fs[(SM_BI >> 2) + col];
                float bb1 = fs[(SM_BI >> 2) + col + 1];
                float v0 = acc[mi][ni][0] + bb0;
                float v1 = acc[mi][ni][1] + bb1;
                float v2 = acc[mi][ni][2] + bb0;
                float v3 = acc[mi][ni][3] + bb1;
                if (row0 < NN) {
                    *(float2*)(C + (size_t)row0 * 128 + col) = make_float2(v0, v1);
                    s0[ni] += v0; s1[ni] += v1; q0[ni] += v0 * v0; q1[ni] += v1 * v1;
                }
                if (row1 < NN) {
                    *(float2*)(C + (size_t)row1 * 128 + col) = make_float2(v2, v3);
                    s0[ni] += v2; s1[ni] += v3; q0[ni] += v2 * v2; q1[ni] += v3 * v3;
                }
            }
        }
        #pragma unroll
        for (int ni = 0; ni < 4; ni++) {
            #pragma unroll
            for (int off = 4; off < 32; off <<= 1) {
                s0[ni] += __shfl_xor_sync(0xffffffffu, s0[ni], off);
                s1[ni] += __shfl_xor_sync(0xffffffffu, s1[ni], off);
                q0[ni] += __shfl_xor_sync(0xffffffffu, q0[ni], off);
                q1[ni] += __shfl_xor_sync(0xffffffffu, q1[ni], off);
            }
            if (lane < 4) {
                int col = wn * 32 + ni * 8 + lane * 2;
                atomicAdd(&fs[(SM_RD >> 2) + col], s0[ni]);
                atomicAdd(&fs[(SM_RD >> 2) + col + 1], s1[ni]);
                atomicAdd(&fs[(SM_RD >> 2) + 128 + col], q0[ni]);
                atomicAdd(&fs[(SM_RD >> 2) + 128 + col + 1], q1[ni]);
            }
        }
    }
    __syncthreads();
    if (tid < 128) {
        atomicAdd(&g_stats[tid], fs[(SM_RD >> 2) + tid]);
        atomicAdd(&g_stats[128 + tid], fs[(SM_RD >> 2) + 128 + tid]);
    }
}

// ---------------- BN finalize ----------------
__global__ void k_finalize(const float* __restrict__ gamma, const float* __restrict__ beta) {
    int t = threadIdx.x;
    float su = g_stats[t];
    float sq = g_stats[128 + t];
    float mean = su * (1.f / NN);
    float var = sq * (1.f / NN) - mean * mean;
    float rstd = rsqrtf(fmaxf(var, 0.f) + 1e-5f);
    float sc = __ldg(&gamma[t]) * rstd;
    g_scale[t] = sc;
    g_shift[t] = __ldg(&beta[t]) - mean * sc;
    g_stats[t] = 0.f;
    g_stats[128 + t] = 0.f;
}

// ---------------- post ----------------
__global__ void k_post(const float* __restrict__ y, float* __restrict__ h, int skipmode) {
    int i = blockIdx.x * blockDim.x + threadIdx.x;
    if (i >= NN * 32) return;
    int c4 = (i & 31) * 4;
    float4 sc = f4ld(g_scale + c4);
    float4 sh = f4ld(g_shift + c4);
    float4 v = ((const float4*)y)[i];
    v.x = fmaxf(fmaf(v.x, sc.x, sh.x), 0.f);
    v.y = fmaxf(fmaf(v.y, sc.y, sh.y), 0.f);
    v.z = fmaxf(fmaf(v.z, sc.z, sh.z), 0.f);
    v.w = fmaxf(fmaf(v.w, sc.w, sh.w), 0.f);
    ((float4*)h)[i] = v;
    if (skipmode == 1) {
        ((float4*)g_skip)[i] = v;
    } else if (skipmode == 2) {
        float4 s = ((float4*)g_skip)[i];
        s.x += v.x; s.y += v.y; s.z += v.z; s.w += v.w;
        ((float4*)g_skip)[i] = s;
    }
}

// ---------------- final ----------------
__global__ void k_final(const float* __restrict__ y, const float* __restrict__ Wr2,
                        const float* __restrict__ br2, float* __restrict__ out) {
    __shared__ float w[128];
    if (threadIdx.x < 128) w[threadIdx.x] = Wr2[threadIdx.x];
    __syncthreads();
    int gt = blockIdx.x * blockDim.x + threadIdx.x;
    int n = gt >> 5;
    int lane = gt & 31;
    if (n >= NN) return;
    float4 v = ((const float4*)y)[(size_t)n * 32 + lane];
    float4 sc = f4ld(g_scale + lane * 4);
    float4 sh = f4ld(g_shift + lane * 4);
    float d = fmaxf(fmaf(v.x, sc.x, sh.x), 0.f) * w[lane * 4 + 0]
            + fmaxf(fmaf(v.y, sc.y, sh.y), 0.f) * w[lane * 4 + 1]
            + fmaxf(fmaf(v.z, sc.z, sh.z), 0.f) * w[lane * 4 + 2]
            + fmaxf(fmaf(v.w, sc.w, sh.w), 0.f) * w[lane * 4 + 3];
    #pragma unroll
    for (int off = 16; off > 0; off >>= 1)
        d += __shfl_xor_sync(0xffffffffu, d, off);
    if (lane == 0) out[n] = 1.f / (1.f + expf(-(d + __ldg(br2))));
}

// ---------------- host ----------------
extern "C" void kernel_launch(void* const* d_in, const int* in_sizes, int n_in,
                              void* d_out, int out_size) {
    const float* x     = (const float*)d_in[0];
    const int*   ei    = (const int*)d_in[1];
    const float* eps   = (const float*)d_in[2];
    const float* W1_0  = (const float*)d_in[3];
    const float* b1_0  = (const float*)d_in[4];
    const float* W1    = (const float*)d_in[5];
    const float* b1    = (const float*)d_in[6];
    const float* g_in  = (const float*)d_in[7];
    const float* be_in = (const float*)d_in[8];
    const float* W2    = (const float*)d_in[9];
    const float* b2    = (const float*)d_in[10];
    const float* g_out = (const float*)d_in[11];
    const float* be_out= (const float*)d_in[12];
    const float* Wr1   = (const float*)d_in[13];
    const float* br1   = (const float*)d_in[14];
    const float* gr    = (const float*)d_in[15];
    const float* ber   = (const float*)d_in[16];
    const float* Wr2   = (const float*)d_in[17];
    const float* br2   = (const float*)d_in[18];
    const int* srcp = ei;
    const int* dstp = ei + NE;

    float *h, *z, *y1, *skip, *z0;
    __nv_bfloat16 *bh, *bl;
    cudaGetSymbolAddress((void**)&h, g_h);
    cudaGetSymbolAddress((void**)&z, g_z);
    cudaGetSymbolAddress((void**)&y1, g_y1);
    cudaGetSymbolAddress((void**)&skip, g_skip);
    cudaGetSymbolAddress((void**)&z0, g_z0);
    cudaGetSymbolAddress((void**)&bh, g_Bh);
    cudaGetSymbolAddress((void**)&bl, g_Bl);

    cudaFuncSetAttribute(k_mgemm<0,16>,  cudaFuncAttributeMaxDynamicSharedMemorySize, SMEM_MG);
    cudaFuncSetAttribute(k_mgemm<0,128>, cudaFuncAttributeMaxDynamicSharedMemorySize, SMEM_MG);
    cudaFuncSetAttribute(k_mgemm<1,128>, cudaFuncAttributeMaxDynamicSharedMemorySize, SMEM_MG);
    cudaFuncSetAttribute(k_mgemm<2,128>, cudaFuncAttributeMaxDynamicSharedMemorySize, SMEM_MG);

    // CSR build + stats zero + weight prep
    k_zero<<<(NN + 255) / 256, 256>>>();
    k_hist<<<(NE + 255) / 256, 256>>>(dstp);
    k_scan1<<<NB_SCAN, 256>>>();
    k_scan2<<<1, 512>>>();
    k_scan3<<<NB_SCAN, 256>>>();
    k_fill<<<(NE + 255) / 256, 256>>>(srcp, dstp);
    {
        dim3 g((BIMG + 255) / 256, 17);
        k_prepw<<<g, 256>>>(W1_0, W1, W2, Wr1);
    }

    for (int i = 0; i < NL; i++) {
        if (i == 0)
            k_agg0<<<(NN * 4 + 255) / 256, 256>>>(x, z0, eps);
        else
            k_agg<<<(NN * 32 + 255) / 256, 256>>>(h, z, eps, i);

        const float* ba = (i == 0) ? b1_0 : (b1 + (size_t)(i - 1) * HIDD);
        int imgA = (i == 0) ? 0 : i;
        if (i == 0)
            k_mgemm<0,16><<<148, 256, SMEM_MG>>>(z0, bh, bl, ba, y1);
        else
            k_mgemm<0,128><<<148, 256, SMEM_MG>>>(z, bh + (size_t)imgA * BIMG,
                                                  bl + (size_t)imgA * BIMG, ba, y1);
        k_finalize<<<1, 128>>>(g_in + (size_t)i * HIDD, be_in + (size_t)i * HIDD);

        int imgB = 8 + i;
        k_mgemm<1,128><<<148, 256, SMEM_MG>>>(y1, bh + (size_t)imgB * BIMG,
                                              bl + (size_t)imgB * BIMG,
                                              b2 + (size_t)i * HIDD, z);
        k_finalize<<<1, 128>>>(g_out + (size_t)i * HIDD, be_out + (size_t)i * HIDD);

        int sm = (i % 2 == 1) ? ((i == 1) ? 1 : 2) : 0;
        k_post<<<(NN * 32 + 255) / 256, 256>>>(z, h, sm);
    }

    // regressor
    k_mgemm<2,128><<<148, 256, SMEM_MG>>>(skip, bh + (size_t)16 * BIMG,
                                          bl + (size_t)16 * BIMG, br1, y1);
    k_finalize<<<1, 128>>>(gr, ber);
    k_final<<<(NN * 32 + 255) / 256, 256>>>(y1, Wr2, br2, (float*)d_out);
}